// round 8
// baseline (speedup 1.0000x reference)
#include <cuda_runtime.h>
#include <math.h>

// Problem constants
#define BB 64
#define TT 2048
#define DD 256
#define VV 256

// Scratch (device globals: allocation-free per harness rules)
__device__ float g_WxE[VV * DD];                       // [v][e]  = E[v] @ Wx^T
__device__ float g_GateE[VV * DD];                     // [v][e]  = sigmoid(E[v] @ Wz^T)
__device__ float g_Y[(long long)BB * TT * DD];         // [b][t][d] = h_t * gate_t  (128 MB)

// ---------------------------------------------------------------------------
// Packed fp32x2 helpers
// ---------------------------------------------------------------------------
__device__ __forceinline__ unsigned long long ffma2(unsigned long long a,
                                                    unsigned long long b,
                                                    unsigned long long c) {
    unsigned long long d;
    asm("fma.rn.f32x2 %0, %1, %2, %3;" : "=l"(d) : "l"(a), "l"(b), "l"(c));
    return d;
}
__device__ __forceinline__ unsigned long long packf2(float lo, float hi) {
    unsigned long long d;
    asm("mov.b64 %0, {%1, %2};" : "=l"(d) : "f"(lo), "f"(hi));
    return d;
}
__device__ __forceinline__ float2 unpackf2(unsigned long long v) {
    float lo, hi;
    asm("mov.b64 {%0, %1}, %2;" : "=f"(lo), "=f"(hi) : "l"(v));
    return make_float2(lo, hi);
}

// ---------------------------------------------------------------------------
// Cluster / mbarrier helpers
// ---------------------------------------------------------------------------
__device__ __forceinline__ unsigned smem_u32(const void* p) {
    return (unsigned)__cvta_generic_to_shared(p);
}
__device__ __forceinline__ unsigned mapa_u32(unsigned addr, unsigned rank) {
    unsigned r;
    asm("mapa.shared::cluster.u32 %0, %1, %2;" : "=r"(r) : "r"(addr), "r"(rank));
    return r;
}
__device__ __forceinline__ unsigned cluster_rank() {
    unsigned r;
    asm("mov.u32 %0, %%cluster_ctarank;" : "=r"(r));
    return r;
}
__device__ __forceinline__ void cluster_sync() {
    asm volatile("barrier.cluster.arrive.aligned;" ::: "memory");
    asm volatile("barrier.cluster.wait.aligned;" ::: "memory");
}
__device__ __forceinline__ void mbar_init(unsigned addr, unsigned count) {
    asm volatile("mbarrier.init.shared.b64 [%0], %1;" :: "r"(addr), "r"(count) : "memory");
}
__device__ __forceinline__ void mbar_arrive_expect_tx(unsigned addr, unsigned bytes) {
    asm volatile("mbarrier.arrive.expect_tx.shared.b64 _, [%0], %1;"
                 :: "r"(addr), "r"(bytes) : "memory");
}
__device__ __forceinline__ void mbar_wait(unsigned addr, unsigned parity) {
    asm volatile(
        "{\n\t"
        ".reg .pred P;\n\t"
        "WAIT_%=:\n\t"
        "mbarrier.try_wait.parity.acquire.cta.shared::cta.b64 P, [%0], %1, 0x989680;\n\t"
        "@P bra.uni DONE_%=;\n\t"
        "bra.uni WAIT_%=;\n\t"
        "DONE_%=:\n\t"
        "}"
        :: "r"(addr), "r"(parity) : "memory");
}
// One-shot bulk SMEM->peer-SMEM copy; signals complete_tx(bytes) on remote mbar.
__device__ __forceinline__ void bulk_copy_cluster(unsigned dst_cluster,
                                                  unsigned src_cta,
                                                  unsigned bytes,
                                                  unsigned rbar_cluster) {
    asm volatile(
        "cp.async.bulk.shared::cluster.shared::cta.mbarrier::complete_tx::bytes "
        "[%0], [%1], %2, [%3];"
        :: "r"(dst_cluster), "r"(src_cta), "r"(bytes), "r"(rbar_cluster)
        : "memory");
}
__device__ __forceinline__ void fence_proxy_async_cta() {
    asm volatile("fence.proxy.async.shared::cta;" ::: "memory");
}
__device__ __forceinline__ void named_bar_sync(int id, int nthreads) {
    asm volatile("bar.sync %0, %1;" :: "r"(id), "r"(nthreads) : "memory");
}

// Fast accurate tanh: tanh(x) = sign(x) * (1-e)/(1+e), e = exp(-2|x|). ~3e-7 rel err.
__device__ __forceinline__ float fast_tanh(float x) {
    float ax = fabsf(x);
    float e = __expf(-2.0f * ax);
    float r = __fdividef(1.0f - e, 1.0f + e);
    return copysignf(r, x);
}

// ---------------------------------------------------------------------------
// Kernel A: token-indexed projection LUTs.
// ---------------------------------------------------------------------------
__global__ void __launch_bounds__(256) precompute_kernel(
    const float* __restrict__ E, const float* __restrict__ Wx,
    const float* __restrict__ Wz) {
    __shared__ __align__(16) float sE[8][DD];
    const int v0 = blockIdx.x * 8;
    const int tid = threadIdx.x;

    for (int i = tid; i < 8 * DD / 4; i += 256)
        ((float4*)&sE[0][0])[i] = ((const float4*)(E + (size_t)v0 * DD))[i];
    __syncthreads();

    const int e = tid;
    float awx[8], awz[8];
#pragma unroll
    for (int v = 0; v < 8; v++) { awx[v] = 0.f; awz[v] = 0.f; }

    const float4* wxr = (const float4*)(Wx + (size_t)e * DD);
    const float4* wzr = (const float4*)(Wz + (size_t)e * DD);
#pragma unroll 4
    for (int dq = 0; dq < DD / 4; dq++) {
        float4 x4 = wxr[dq];
        float4 z4 = wzr[dq];
#pragma unroll
        for (int v = 0; v < 8; v++) {
            float4 e4 = *(const float4*)&sE[v][dq * 4];
            awx[v] = fmaf(x4.x, e4.x, awx[v]);
            awx[v] = fmaf(x4.y, e4.y, awx[v]);
            awx[v] = fmaf(x4.z, e4.z, awx[v]);
            awx[v] = fmaf(x4.w, e4.w, awx[v]);
            awz[v] = fmaf(z4.x, e4.x, awz[v]);
            awz[v] = fmaf(z4.y, e4.y, awz[v]);
            awz[v] = fmaf(z4.z, e4.z, awz[v]);
            awz[v] = fmaf(z4.w, e4.w, awz[v]);
        }
    }
#pragma unroll
    for (int v = 0; v < 8; v++) {
        g_WxE[(size_t)(v0 + v) * DD + e] = awx[v];
        g_GateE[(size_t)(v0 + v) * DD + e] = 1.f / (1.f + expf(-awz[v]));
    }
}

// ---------------------------------------------------------------------------
// Kernel B: the recurrence, COLUMN-SPLIT version.
// One 2-CTA cluster per batch (grid 128, block 256).
// CTA rank r holds Wh[:, r*128:(r+1)*128] (all 256 rows, its column half) in
// registers, and keeps only its OWN half of h (h[r*128 .. r*128+128)) in smem.
// Thread tid owns one full output row:
//   tid <  128 (LOW  warps 0-3): row = rank*128 + tid      (our rows)
//   tid >= 128 (HIGH warps 4-7): row = (rank^1)*128 + tid-128 (peer's rows)
// Per step:
//   all:   partial = W[row, cols_r] . h_r      (LOCAL data only -> no wait!)
//   HIGH:  STS partial -> send_buf; bar.sync(4 warps); tid==128 bulk-copies
//          512B to peer's recv_buf + peer mbarrier. Hi-wid arbiter priority
//          makes HIGH warps' matvec finish first -> send leaves early, and
//          the flight overlaps LOW warps' matvec / LUT loads / Y store.
//   LOW:   mbar_wait(peer partials for OUR rows); h = tanh(wx + partial + recv);
//          write s_h[next], write Y. No shfl, no pair-reduce anywhere.
// ---------------------------------------------------------------------------
__global__ void __launch_bounds__(256, 1) __cluster_dims__(2, 1, 1)
rnn_kernel(const int* __restrict__ tokens, const float* __restrict__ Wh) {
    __shared__ __align__(16) float s_h[2][128];      // our h half, double-buffered
    __shared__ __align__(16) float s_send[2][128];   // partials for peer's rows
    __shared__ __align__(16) float s_recv[2][128];   // peer partials for our rows
    __shared__ __align__(16) int s_tok[TT];
    __shared__ __align__(8) unsigned long long s_bar[2];

    const unsigned rank = cluster_rank();
    const int b = blockIdx.x >> 1;
    const int tid = threadIdx.x;
    const bool low = tid < 128;
    const int lrow = low ? tid : (tid - 128);
    const int row = low ? ((int)rank * 128 + lrow)
                        : ((int)(rank ^ 1) * 128 + lrow);

    // ---- weights: Wh[row, rank*128 + k], k=0..127 -> 64 packed f32x2
    unsigned long long w[64];
    {
        const ulonglong2* wp =
            (const ulonglong2*)(Wh + (size_t)row * DD + (int)rank * 128);
#pragma unroll
        for (int i = 0; i < 32; i++) {
            ulonglong2 q = wp[i];
            w[2 * i] = q.x;
            w[2 * i + 1] = q.y;
        }
    }

    // ---- tokens for this batch
    {
        const int4* tp = (const int4*)(tokens + (size_t)b * TT);
        for (int i = tid; i < TT / 4; i += 256) ((int4*)s_tok)[i] = tp[i];
    }
    // ---- zero h buffers (both)
    if (tid < 256) ((float*)s_h)[tid] = 0.f;

    const unsigned my_send = smem_u32(&s_send[0][0]);
    const unsigned my_recv = smem_u32(&s_recv[0][0]);
    const unsigned my_bar = smem_u32(&s_bar[0]);
    if (tid == 0) {
        mbar_init(my_bar, 1);
        mbar_init(my_bar + 8, 1);
        mbar_arrive_expect_tx(my_bar, 512);      // 512B/step from peer
        mbar_arrive_expect_tx(my_bar + 8, 512);
    }
    __syncthreads();
    cluster_sync();  // mbarrier init visible cluster-wide before any bulk lands

    const unsigned peer_recv = mapa_u32(my_recv, rank ^ 1);
    const unsigned peer_bar = mapa_u32(my_bar, rank ^ 1);

    const size_t ybase = (size_t)b * TT * DD + (size_t)rank * 128;
    unsigned ph0 = 0, ph1 = 0;

    // LUT prefetch (one step ahead) — LOW threads only (they own our rows)
    float wx = 0.f, gate = 0.f;
    if (low) {
        const int tok0 = s_tok[0];
        wx = __ldg(&g_WxE[(size_t)tok0 * DD + row]);
        gate = __ldg(&g_GateE[(size_t)tok0 * DD + row]);
    }

    for (int t = 0; t < TT; t++) {
        const int buf = t & 1;

        // prefetch t+1 LUT rows (in flight during matvec + wait)
        float wx_n = 0.f, gate_n = 0.f;
        if (low) {
            const int tok_n = s_tok[(t + 1 < TT) ? (t + 1) : t];
            wx_n = __ldg(&g_WxE[(size_t)tok_n * DD + row]);
            gate_n = __ldg(&g_GateE[(size_t)tok_n * DD + row]);
        }

        // matvec over OUR h half (local only): 16 LDS.128 + 64 FFMA2.
        // All lanes read identical addresses -> smem broadcast (N=1).
        const ulonglong2* hp = (const ulonglong2*)&s_h[buf][0];
        unsigned long long a0 = 0ull, a1 = 0ull, a2 = 0ull, a3 = 0ull;
#pragma unroll
        for (int i = 0; i < 32; i += 2) {
            ulonglong2 q0 = hp[i];
            ulonglong2 q1 = hp[i + 1];
            a0 = ffma2(w[2 * i + 0], q0.x, a0);
            a1 = ffma2(w[2 * i + 1], q0.y, a1);
            a2 = ffma2(w[2 * i + 2], q1.x, a2);
            a3 = ffma2(w[2 * i + 3], q1.y, a3);
        }
        float2 f0 = unpackf2(a0), f1 = unpackf2(a1);
        float2 f2 = unpackf2(a2), f3 = unpackf2(a3);
        const float partial = ((f0.x + f0.y) + (f1.x + f1.y)) +
                              ((f2.x + f2.y) + (f3.x + f3.y));

        if (!low) {
            // HIGH warps: ship partials for the peer's rows ASAP.
            s_send[buf][lrow] = partial;
            named_bar_sync(1, 128);              // high warps only; drains STS
            if (tid == 128) {
                fence_proxy_async_cta();         // STS visible to async proxy
                bulk_copy_cluster(peer_recv + (unsigned)buf * 512u,
                                  my_send + (unsigned)buf * 512u, 512,
                                  peer_bar + (unsigned)buf * 8u);
            }
        } else {
            // LOW warps: wait for peer's partials for OUR rows, finish h.
            const unsigned barb = my_bar + (unsigned)buf * 8u;
            if (buf == 0) { mbar_wait(barb, ph0); ph0 ^= 1; }
            else          { mbar_wait(barb, ph1); ph1 ^= 1; }
            if (tid == 0) mbar_arrive_expect_tx(barb, 512);  // re-arm for t+2

            const float s = wx + partial + s_recv[buf][lrow];
            const float hn = fast_tanh(s);
            s_h[buf ^ 1][lrow] = hn;
            g_Y[ybase + (size_t)t * DD + lrow] = hn * gate;
            wx = wx_n; gate = gate_n;
        }
        __syncthreads();  // s_h[buf^1] visible to all; orders re-arm before next send
    }
    cluster_sync();  // don't exit while peer smem traffic may be in flight
}

// ---------------------------------------------------------------------------
// Kernel C: logits = Y[131072, 256] @ E^T.  Tiled fp32 GEMM, f32x2 packed.
// Block tile 128x256, 256 threads, micro-tile 8x16, strided rows (conflict-free).
// ---------------------------------------------------------------------------
__global__ void __launch_bounds__(256) head_kernel(
    const float* __restrict__ E, float* __restrict__ out) {
    __shared__ __align__(16) float sY[128][33];    // [m][k]
    __shared__ __align__(16) float sEt[32][258];   // [k][v]

    const int m0 = blockIdx.x * 128;
    const int tid = threadIdx.x;
    const int tm = tid & 15;   // row slot: rows tm + 16*i
    const int tn = tid >> 4;   // col group: cols [tn*16, tn*16+16)

    unsigned long long acc[8][8];
#pragma unroll
    for (int i = 0; i < 8; i++)
#pragma unroll
        for (int c = 0; c < 8; c++) acc[i][c] = 0ull;

    for (int k0 = 0; k0 < DD; k0 += 32) {
        __syncthreads();
#pragma unroll
        for (int i = 0; i < 4; i++) {
            int idx = tid + i * 256;       // 0..1023
            int mm = idx >> 3, kq = idx & 7;
            float4 v = *(const float4*)&g_Y[(size_t)(m0 + mm) * DD + k0 + kq * 4];
            sY[mm][kq * 4 + 0] = v.x;
            sY[mm][kq * 4 + 1] = v.y;
            sY[mm][kq * 4 + 2] = v.z;
            sY[mm][kq * 4 + 3] = v.w;
        }
#pragma unroll
        for (int i = 0; i < 8; i++) {
            int idx = i * 256 + tid;
            int v = idx >> 3, kq = idx & 7;
            float4 e4 = *(const float4*)&E[(size_t)v * DD + k0 + kq * 4];
            sEt[kq * 4 + 0][v] = e4.x;
            sEt[kq * 4 + 1][v] = e4.y;
            sEt[kq * 4 + 2][v] = e4.z;
            sEt[kq * 4 + 3][v] = e4.w;
        }
        __syncthreads();

#pragma unroll
        for (int k = 0; k < 32; k++) {
            unsigned long long ap[8];
#pragma unroll
            for (int i = 0; i < 8; i++) {
                const float a = sY[tm + 16 * i][k];
                ap[i] = packf2(a, a);
            }
            const unsigned long long* bp =
                (const unsigned long long*)&sEt[k][tn * 16];
            unsigned long long bv[8];
#pragma unroll
            for (int c = 0; c < 8; c++) bv[c] = bp[c];
#pragma unroll
            for (int i = 0; i < 8; i++)
#pragma unroll
                for (int c = 0; c < 8; c++)
                    acc[i][c] = ffma2(ap[i], bv[c], acc[i][c]);
        }
    }

#pragma unroll
    for (int i = 0; i < 8; i++) {
        float* orow = out + (size_t)(m0 + tm + 16 * i) * VV + tn * 16;
#pragma unroll
        for (int c = 0; c < 8; c++) {
            float2 v = unpackf2(acc[i][c]);
            *(float2*)&orow[2 * c] = v;
        }
    }
}

// ---------------------------------------------------------------------------
extern "C" void kernel_launch(void* const* d_in, const int* in_sizes, int n_in,
                              void* d_out, int out_size) {
    const int* tokens = (const int*)d_in[0];
    const float* E = (const float*)d_in[1];
    const float* Wx = (const float*)d_in[2];
    const float* Wh = (const float*)d_in[3];
    const float* Wz = (const float*)d_in[4];
    float* out = (float*)d_out;

    precompute_kernel<<<VV / 8, 256>>>(E, Wx, Wz);
    rnn_kernel<<<BB * 2, 256>>>(tokens, Wh);           // 64 clusters x 2 CTAs
    head_kernel<<<(BB * TT) / 128, 256>>>(E, out);
}